// round 2
// baseline (speedup 1.0000x reference)
#include <cuda_runtime.h>
#include <cuda_bf16.h>

#define EMB   64
#define NSPH  16
#define KMAX  24
#define MAX_EDGES 131072

// Scratch (device globals — no allocation allowed in kernel_launch)
__device__ int   g_start[MAX_EDGES];
__device__ int   g_count[MAX_EDGES];
__device__ float g_wT[EMB * EMB];   // wT[i*64 + d] = w[d*64 + i]

// Prep: per-edge triplet run boundaries (id_reduce is sorted, runs contiguous)
// plus weight transpose so the main kernel's w-loads are coalesced over d.
__global__ void prep_kernel(const int* __restrict__ id_reduce,
                            const int* __restrict__ Kidx,
                            const float* __restrict__ w,
                            int nT)
{
    int t = blockIdx.x * blockDim.x + threadIdx.x;
    if (t < EMB * EMB) {
        int i = t >> 6;
        int d = t & 63;
        g_wT[i * EMB + d] = w[d * EMB + i];
    }
    if (t < nT) {
        int e = id_reduce[t];
        if (t == 0 || id_reduce[t - 1] != e) g_start[e] = t;
        if (t == nT - 1 || id_reduce[t + 1] != e) g_count[e] = Kidx[t] + 1;
    }
}

__global__ void __launch_bounds__(256)
main_kernel(const float* __restrict__ rbf,
            const float* __restrict__ sph,
            const float* __restrict__ m,
            const int*   __restrict__ Kidx,
            float* __restrict__ out)
{
    const int e   = blockIdx.x;
    const int tid = threadIdx.x;
    const int d   = tid & 63;
    const int sg  = tid >> 6;      // 0..3 (warp-uniform: warps 0,1 -> sg 0, etc.)

    __shared__ __align__(16) float sphT[KMAX][NSPH];   // [k][s]
    __shared__ __align__(16) float m_sm[KMAX][EMB];    // [t][d]
    __shared__ __align__(16) float rbf_sm[EMB][NSPH];  // [i][s]
    __shared__ __align__(16) float A_sm[NSPH][EMB];    // [s][d]
    __shared__ float red[4][EMB];
    __shared__ int   k_sm[KMAX];

    const int start = g_start[e];
    int count = g_count[e];
    if (count > KMAX) count = KMAX;

    // ---- cooperative loads ----
    const float* rbf_e = rbf + (size_t)e * (EMB * NSPH);
    #pragma unroll
    for (int idx = tid; idx < EMB * NSPH; idx += 256)
        ((float*)rbf_sm)[idx] = rbf_e[idx];

    const float* sph_e = sph + (size_t)e * (NSPH * KMAX);
    for (int idx = tid; idx < NSPH * KMAX; idx += 256) {
        int s = idx / KMAX;
        int k = idx - s * KMAX;
        sphT[k][s] = sph_e[idx];
    }

    const float* m_e = m + (size_t)start * EMB;
    for (int idx = tid; idx < count * EMB; idx += 256) {
        int t = idx >> 6;
        m_sm[t][idx & 63] = m_e[idx];
    }

    if (tid < count) k_sm[tid] = Kidx[start + tid];
    __syncthreads();

    // ---- stage 1: A[s][d] = sum_t sph[s, k_t] * m[t][d], this thread owns s in [4*sg, 4*sg+4) ----
    float a0 = 0.f, a1 = 0.f, a2 = 0.f, a3 = 0.f;
    #pragma unroll 4
    for (int t = 0; t < count; t++) {
        float val = m_sm[t][d];
        int   k   = k_sm[t];
        float4 sp = *(const float4*)&sphT[k][sg * 4];
        a0 += sp.x * val;
        a1 += sp.y * val;
        a2 += sp.z * val;
        a3 += sp.w * val;
    }
    A_sm[sg * 4 + 0][d] = a0;
    A_sm[sg * 4 + 1][d] = a1;
    A_sm[sg * 4 + 2][d] = a2;
    A_sm[sg * 4 + 3][d] = a3;
    __syncthreads();

    // ---- stage 2: out[e,d] = sum_i wT[i][d] * (sum_s rbf[i][s] * A[s][d]) ----
    float a[NSPH];
    #pragma unroll
    for (int s = 0; s < NSPH; s++) a[s] = A_sm[s][d];

    float partial = 0.f;
    const int i0 = sg * 16;
    #pragma unroll
    for (int ii = 0; ii < 16; ii++) {
        const int i = i0 + ii;
        float4 r0 = *(const float4*)&rbf_sm[i][0];
        float4 r1 = *(const float4*)&rbf_sm[i][4];
        float4 r2 = *(const float4*)&rbf_sm[i][8];
        float4 r3 = *(const float4*)&rbf_sm[i][12];
        float r = r0.x * a[0]  + r0.y * a[1]  + r0.z * a[2]  + r0.w * a[3]
                + r1.x * a[4]  + r1.y * a[5]  + r1.z * a[6]  + r1.w * a[7]
                + r2.x * a[8]  + r2.y * a[9]  + r2.z * a[10] + r2.w * a[11]
                + r3.x * a[12] + r3.y * a[13] + r3.z * a[14] + r3.w * a[15];
        partial += g_wT[i * EMB + d] * r;
    }

    red[sg][d] = partial;
    __syncthreads();
    if (sg == 0)
        out[(size_t)e * EMB + d] = red[0][d] + red[1][d] + red[2][d] + red[3][d];
}

extern "C" void kernel_launch(void* const* d_in, const int* in_sizes, int n_in,
                              void* d_out, int out_size)
{
    const float* rbf  = (const float*)d_in[0];
    const float* sph  = (const float*)d_in[1];
    const float* m    = (const float*)d_in[2];
    const float* w    = (const float*)d_in[3];
    const int*   idr  = (const int*)d_in[4];
    const int*   kidx = (const int*)d_in[5];

    const int nEdges = in_sizes[0] / (EMB * NSPH);
    const int nT     = in_sizes[4];

    int prep_elems = nT > (EMB * EMB) ? nT : (EMB * EMB);
    int prep_blocks = (prep_elems + 255) / 256;
    prep_kernel<<<prep_blocks, 256>>>(idr, kidx, w, nT);

    main_kernel<<<nEdges, 256>>>(rbf, sph, m, kidx, (float*)d_out);
}

// round 3
// speedup vs baseline: 1.2212x; 1.2212x over previous
#include <cuda_runtime.h>

#define EMB   64
#define NSPH  16
#define KMAX  24
#define MAX_EDGES 131072
#define NWARPS_BLK 4
#define NBLOCKS 608

typedef unsigned long long u64;

__device__ int g_start[MAX_EDGES];
__device__ int g_count[MAX_EDGES];

// Per-edge triplet run boundaries (id_reduce is sorted, runs contiguous).
__global__ void prep_kernel(const int* __restrict__ id_reduce,
                            const int* __restrict__ Kidx, int nT)
{
    int t = blockIdx.x * blockDim.x + threadIdx.x;
    if (t < nT) {
        int e = id_reduce[t];
        if (t == 0 || id_reduce[t - 1] != e) g_start[e] = t;
        if (t == nT - 1 || id_reduce[t + 1] != e) g_count[e] = Kidx[t] + 1;
    }
}

// ---- packed f32x2 helpers (sm_103a dual-fp32 pipe) ----
__device__ __forceinline__ u64 pack2(float x) {
    u64 r; asm("mov.b64 %0, {%1, %1};" : "=l"(r) : "f"(x)); return r;
}
__device__ __forceinline__ u64 ffma2(u64 a, u64 b, u64 c) {
    u64 d; asm("fma.rn.f32x2 %0, %1, %2, %3;" : "=l"(d) : "l"(a), "l"(b), "l"(c)); return d;
}
__device__ __forceinline__ u64 fmul2(u64 a, u64 b) {
    u64 d; asm("mul.rn.f32x2 %0, %1, %2;" : "=l"(d) : "l"(a), "l"(b)); return d;
}
__device__ __forceinline__ u64 fadd2(u64 a, u64 b) {
    u64 d; asm("add.rn.f32x2 %0, %1, %2;" : "=l"(d) : "l"(a), "l"(b)); return d;
}

// One warp per edge. Lane layout: db = lane&7 (d in [8db,8db+8), as 4 f32x2
// pairs), sb = lane>>3 (s in [4sb,4sb+4)). Stage-1 A-tile and stage-2 B-tile
// share the lane mapping, so the Hadamard contraction is register-resident.
__global__ void __launch_bounds__(128, 4)
main_kernel(const float* __restrict__ rbf,
            const float* __restrict__ sph,
            const float* __restrict__ m,
            const float* __restrict__ w,
            const int*   __restrict__ Kidx,
            float* __restrict__ out, int nEdges)
{
    __shared__ float Wt[EMB * EMB];                     // Wt[i*64+d] = w[d*64+i]
    __shared__ float rbf_sm[NWARPS_BLK][EMB * NSPH];    // [i*16+s]
    __shared__ u64   sph_dup[NWARPS_BLK][NSPH * KMAX];  // [s*24+k], value duplicated {v,v}

    const int tid  = threadIdx.x;
    const int wrp  = tid >> 5;
    const int lane = tid & 31;
    const int db   = lane & 7;
    const int sb   = lane >> 3;

    // W transpose into shared, once per block (amortized over many edges)
    for (int idx = tid; idx < EMB * EMB; idx += 128) {
        int d = idx >> 6, i = idx & 63;
        Wt[i * EMB + d] = w[idx];                       // w is [d][0][i]
    }
    __syncthreads();

    const int gwarp  = blockIdx.x * NWARPS_BLK + wrp;
    const int nwarps = gridDim.x * NWARPS_BLK;
    float* rbf_s = rbf_sm[wrp];
    u64*   sph_s = sph_dup[wrp];

    for (int e = gwarp; e < nEdges; e += nwarps) {
        __syncwarp();   // WAR guard on per-warp smem buffers

        // fill rbf tile (64x16 floats), coalesced float4
        const float4* rbf_e = (const float4*)(rbf + (size_t)e * (EMB * NSPH));
        #pragma unroll
        for (int it = 0; it < 8; it++)
            ((float4*)rbf_s)[it * 32 + lane] = rbf_e[it * 32 + lane];

        // fill sph tile duplicated into f32x2 (16x24)
        const float4* sph_e = (const float4*)(sph + (size_t)e * (NSPH * KMAX));
        #pragma unroll
        for (int it = 0; it < 3; it++) {
            float4 v = sph_e[it * 32 + lane];
            int o = (it * 32 + lane) * 4;
            sph_s[o + 0] = pack2(v.x);
            sph_s[o + 1] = pack2(v.y);
            sph_s[o + 2] = pack2(v.z);
            sph_s[o + 3] = pack2(v.w);
        }

        const int start = g_start[e];
        const int count = g_count[e];
        int kreg = 0;
        if (lane < count) kreg = Kidx[start + lane];
        __syncwarp();

        // ---- stage 1: A[s][d] = sum_t sph[s][k_t] * m[t][d] (register tile) ----
        u64 accA[4][4];
        #pragma unroll
        for (int s = 0; s < 4; s++)
            #pragma unroll
            for (int dp = 0; dp < 4; dp++) accA[s][dp] = 0ull;

        const float4* m_base = (const float4*)(m + (size_t)start * EMB + db * 8);
        #pragma unroll 2
        for (int t = 0; t < count; t++) {
            int k = __shfl_sync(0xffffffffu, kreg, t);
            float4 m0 = m_base[t * 16 + 0];
            float4 m1 = m_base[t * 16 + 1];
            u64 m2[4];
            m2[0] = ((const u64*)&m0)[0];
            m2[1] = ((const u64*)&m0)[1];
            m2[2] = ((const u64*)&m1)[0];
            m2[3] = ((const u64*)&m1)[1];
            #pragma unroll
            for (int s = 0; s < 4; s++) {
                u64 sp = sph_s[(4 * sb + s) * KMAX + k];
                #pragma unroll
                for (int dp = 0; dp < 4; dp++)
                    accA[s][dp] = ffma2(sp, m2[dp], accA[s][dp]);
            }
        }

        // ---- stage 2: B[d][s] = sum_i Wt[i][d] * rbf[i][s] (register tile) ----
        u64 accB[4][4];
        #pragma unroll
        for (int s = 0; s < 4; s++)
            #pragma unroll
            for (int dp = 0; dp < 4; dp++) accB[dp][s] = 0ull;

        #pragma unroll 8
        for (int k = 0; k < EMB; k++) {
            const float4* wrow = (const float4*)(Wt + k * EMB + db * 8);
            float4 w0 = wrow[0];
            float4 w1 = wrow[1];
            u64 w2[4];
            w2[0] = ((const u64*)&w0)[0];
            w2[1] = ((const u64*)&w0)[1];
            w2[2] = ((const u64*)&w1)[0];
            w2[3] = ((const u64*)&w1)[1];
            float4 r4 = *(const float4*)(rbf_s + k * NSPH + 4 * sb);
            u64 rd[4] = { pack2(r4.x), pack2(r4.y), pack2(r4.z), pack2(r4.w) };
            #pragma unroll
            for (int s = 0; s < 4; s++)
                #pragma unroll
                for (int dp = 0; dp < 4; dp++)
                    accB[dp][s] = ffma2(w2[dp], rd[s], accB[dp][s]);
        }

        // ---- Hadamard + s-reduction, all in registers ----
        u64 osum[4];
        #pragma unroll
        for (int dp = 0; dp < 4; dp++) {
            u64 acc = fmul2(accB[dp][0], accA[0][dp]);
            acc = ffma2(accB[dp][1], accA[1][dp], acc);
            acc = ffma2(accB[dp][2], accA[2][dp], acc);
            acc = ffma2(accB[dp][3], accA[3][dp], acc);
            osum[dp] = acc;
        }
        // reduce over the 4 sb lanes (xor 8, 16)
        #pragma unroll
        for (int off = 8; off <= 16; off <<= 1) {
            #pragma unroll
            for (int dp = 0; dp < 4; dp++)
                osum[dp] = fadd2(osum[dp],
                                 __shfl_xor_sync(0xffffffffu, osum[dp], off));
        }

        if (sb == 0) {
            float4 o0, o1;
            ((u64*)&o0)[0] = osum[0];
            ((u64*)&o0)[1] = osum[1];
            ((u64*)&o1)[0] = osum[2];
            ((u64*)&o1)[1] = osum[3];
            float4* op = (float4*)(out + (size_t)e * EMB + db * 8);
            op[0] = o0;
            op[1] = o1;
        }
    }
}

extern "C" void kernel_launch(void* const* d_in, const int* in_sizes, int n_in,
                              void* d_out, int out_size)
{
    const float* rbf  = (const float*)d_in[0];
    const float* sph  = (const float*)d_in[1];
    const float* m    = (const float*)d_in[2];
    const float* w    = (const float*)d_in[3];
    const int*   idr  = (const int*)d_in[4];
    const int*   kidx = (const int*)d_in[5];

    const int nEdges = in_sizes[0] / (EMB * NSPH);
    const int nT     = in_sizes[4];

    prep_kernel<<<(nT + 255) / 256, 256>>>(idr, kidx, nT);
    main_kernel<<<NBLOCKS, 128>>>(rbf, sph, m, w, kidx, (float*)d_out, nEdges);
}

// round 4
// speedup vs baseline: 1.5129x; 1.2388x over previous
#include <cuda_runtime.h>

#define EMB   64
#define NSPH  16
#define KMAX  24
#define MAX_EDGES 131072
#define NBLOCKS 456   // 3 per SM * 152

typedef unsigned long long u64;

__device__ int g_start[MAX_EDGES];
__device__ int g_count[MAX_EDGES];

// Per-edge triplet run boundaries (id_reduce sorted, runs contiguous; Kidx
// within each run is 0..count-1, so stage 1 is a dense contiguous GEMM).
__global__ void prep_kernel(const int* __restrict__ id_reduce,
                            const int* __restrict__ Kidx, int nT)
{
    int t = blockIdx.x * blockDim.x + threadIdx.x;
    if (t < nT) {
        int e = id_reduce[t];
        if (t == 0 || id_reduce[t - 1] != e) g_start[e] = t;
        if (t == nT - 1 || id_reduce[t + 1] != e) g_count[e] = Kidx[t] + 1;
    }
}

// ---- packed f32x2 helpers ----
__device__ __forceinline__ u64 pack2(float x) {
    u64 r; asm("mov.b64 %0, {%1, %1};" : "=l"(r) : "f"(x)); return r;
}
__device__ __forceinline__ u64 ffma2(u64 a, u64 b, u64 c) {
    u64 d; asm("fma.rn.f32x2 %0, %1, %2, %3;" : "=l"(d) : "l"(a), "l"(b), "l"(c)); return d;
}
__device__ __forceinline__ u64 fmul2(u64 a, u64 b) {
    u64 d; asm("mul.rn.f32x2 %0, %1, %2;" : "=l"(d) : "l"(a), "l"(b)); return d;
}
__device__ __forceinline__ u64 fadd2(u64 a, u64 b) {
    u64 d; asm("add.rn.f32x2 %0, %1, %2;" : "=l"(d) : "l"(a), "l"(b)); return d;
}

// One warp handles an edge PAIR. Lane layout: db = lane&7 (d in [8db,8db+8) as
// 4 f32x2), sb = lane>>3 (s in [4sb,4sb+4)). Stage-2 B-tiles for both edges are
// computed in one k-loop so each Wt smem read is amortized over 2 edges.
// Stage-1 A-tile per edge is a dense GEMM over contiguous m rows (k == t).
// Hadamard + s-reduction happen in registers + shfl.
__global__ void __launch_bounds__(128, 3)
main_kernel(const float* __restrict__ rbf,
            const float* __restrict__ sph,
            const float* __restrict__ m,
            const float* __restrict__ w,
            float* __restrict__ out, int nEdges)
{
    __shared__ float Wt[EMB * EMB];   // Wt[i*64+d] = w[d*64+i]

    const int tid  = threadIdx.x;
    const int lane = tid & 31;
    const int db   = lane & 7;
    const int sb   = lane >> 3;

    for (int idx = tid; idx < EMB * EMB; idx += 128) {
        int d = idx >> 6, i = idx & 63;
        Wt[i * EMB + d] = w[idx];
    }
    __syncthreads();

    const int gwarp  = blockIdx.x * 4 + (tid >> 5);
    const int nwarps = gridDim.x * 4;
    const int npairs = (nEdges + 1) >> 1;

    for (int p = gwarp; p < npairs; p += nwarps) {
        const int e0 = 2 * p;
        const int e1 = (2 * p + 1 < nEdges) ? 2 * p + 1 : e0;

        // ---- stage 2: B[e][d][s] = sum_i Wt[i][d] * rbf[e][i][s] ----
        u64 accB0[4][4], accB1[4][4];   // [dp][s]
        #pragma unroll
        for (int dp = 0; dp < 4; dp++)
            #pragma unroll
            for (int s = 0; s < 4; s++) { accB0[dp][s] = 0ull; accB1[dp][s] = 0ull; }

        const float4* rbf0 = (const float4*)(rbf + (size_t)e0 * (EMB * NSPH) + sb * 4);
        const float4* rbf1 = (const float4*)(rbf + (size_t)e1 * (EMB * NSPH) + sb * 4);

        #pragma unroll 8
        for (int k = 0; k < EMB; k++) {
            const float4* wrow = (const float4*)(Wt + k * EMB + db * 8);
            float4 wa = wrow[0];
            float4 wb = wrow[1];
            u64 w2[4];
            w2[0] = ((const u64*)&wa)[0];
            w2[1] = ((const u64*)&wa)[1];
            w2[2] = ((const u64*)&wb)[0];
            w2[3] = ((const u64*)&wb)[1];

            float4 r0 = rbf0[k * 4];
            float4 r1 = rbf1[k * 4];
            u64 rd0[4] = { pack2(r0.x), pack2(r0.y), pack2(r0.z), pack2(r0.w) };
            u64 rd1[4] = { pack2(r1.x), pack2(r1.y), pack2(r1.z), pack2(r1.w) };

            #pragma unroll
            for (int dp = 0; dp < 4; dp++)
                #pragma unroll
                for (int s = 0; s < 4; s++) {
                    accB0[dp][s] = ffma2(w2[dp], rd0[s], accB0[dp][s]);
                    accB1[dp][s] = ffma2(w2[dp], rd1[s], accB1[dp][s]);
                }
        }

        // ---- stage 1 + Hadamard per edge ----
        #pragma unroll 1
        for (int ei = 0; ei < 2; ei++) {
            const int e = ei ? e1 : e0;
            if (ei && e1 == e0) break;

            const int start = g_start[e];
            const int count = g_count[e];

            const float* sph_e = sph + (size_t)e * (NSPH * KMAX);
            const float* s0p = sph_e + (4 * sb + 0) * KMAX;
            const float* s1p = sph_e + (4 * sb + 1) * KMAX;
            const float* s2p = sph_e + (4 * sb + 2) * KMAX;
            const float* s3p = sph_e + (4 * sb + 3) * KMAX;

            u64 accA[4][4];   // [s][dp]
            #pragma unroll
            for (int s = 0; s < 4; s++)
                #pragma unroll
                for (int dp = 0; dp < 4; dp++) accA[s][dp] = 0ull;

            const float4* m_base = (const float4*)(m + (size_t)start * EMB + db * 8);

            const int t4 = count & ~3;
            for (int t0 = 0; t0 < t4; t0 += 4) {
                float4 sp0 = *(const float4*)(s0p + t0);
                float4 sp1 = *(const float4*)(s1p + t0);
                float4 sp2 = *(const float4*)(s2p + t0);
                float4 sp3 = *(const float4*)(s3p + t0);
                #pragma unroll
                for (int j = 0; j < 4; j++) {
                    float4 ma = m_base[(t0 + j) * 16 + 0];
                    float4 mb = m_base[(t0 + j) * 16 + 1];
                    u64 m2[4];
                    m2[0] = ((const u64*)&ma)[0];
                    m2[1] = ((const u64*)&ma)[1];
                    m2[2] = ((const u64*)&mb)[0];
                    m2[3] = ((const u64*)&mb)[1];
                    u64 sv[4] = { pack2(((const float*)&sp0)[j]),
                                  pack2(((const float*)&sp1)[j]),
                                  pack2(((const float*)&sp2)[j]),
                                  pack2(((const float*)&sp3)[j]) };
                    #pragma unroll
                    for (int s = 0; s < 4; s++)
                        #pragma unroll
                        for (int dp = 0; dp < 4; dp++)
                            accA[s][dp] = ffma2(sv[s], m2[dp], accA[s][dp]);
                }
            }
            for (int t = t4; t < count; t++) {
                float4 ma = m_base[t * 16 + 0];
                float4 mb = m_base[t * 16 + 1];
                u64 m2[4];
                m2[0] = ((const u64*)&ma)[0];
                m2[1] = ((const u64*)&ma)[1];
                m2[2] = ((const u64*)&mb)[0];
                m2[3] = ((const u64*)&mb)[1];
                u64 sv[4] = { pack2(s0p[t]), pack2(s1p[t]),
                              pack2(s2p[t]), pack2(s3p[t]) };
                #pragma unroll
                for (int s = 0; s < 4; s++)
                    #pragma unroll
                    for (int dp = 0; dp < 4; dp++)
                        accA[s][dp] = ffma2(sv[s], m2[dp], accA[s][dp]);
            }

            // Hadamard + s-reduction
            u64 osum[4];
            #pragma unroll
            for (int dp = 0; dp < 4; dp++) {
                u64 b0 = ei ? accB1[dp][0] : accB0[dp][0];
                u64 b1 = ei ? accB1[dp][1] : accB0[dp][1];
                u64 b2 = ei ? accB1[dp][2] : accB0[dp][2];
                u64 b3 = ei ? accB1[dp][3] : accB0[dp][3];
                u64 acc = fmul2(b0, accA[0][dp]);
                acc = ffma2(b1, accA[1][dp], acc);
                acc = ffma2(b2, accA[2][dp], acc);
                acc = ffma2(b3, accA[3][dp], acc);
                osum[dp] = acc;
            }
            #pragma unroll
            for (int off = 8; off <= 16; off <<= 1)
                #pragma unroll
                for (int dp = 0; dp < 4; dp++)
                    osum[dp] = fadd2(osum[dp],
                                     __shfl_xor_sync(0xffffffffu, osum[dp], off));

            if (sb == 0) {
                float4 o0, o1;
                ((u64*)&o0)[0] = osum[0];
                ((u64*)&o0)[1] = osum[1];
                ((u64*)&o1)[0] = osum[2];
                ((u64*)&o1)[1] = osum[3];
                float4* op = (float4*)(out + (size_t)e * EMB + db * 8);
                op[0] = o0;
                op[1] = o1;
            }
        }
    }
}

extern "C" void kernel_launch(void* const* d_in, const int* in_sizes, int n_in,
                              void* d_out, int out_size)
{
    const float* rbf  = (const float*)d_in[0];
    const float* sph  = (const float*)d_in[1];
    const float* m    = (const float*)d_in[2];
    const float* w    = (const float*)d_in[3];
    const int*   idr  = (const int*)d_in[4];
    const int*   kidx = (const int*)d_in[5];

    const int nEdges = in_sizes[0] / (EMB * NSPH);
    const int nT     = in_sizes[4];

    prep_kernel<<<(nT + 255) / 256, 256>>>(idr, kidx, nT);
    main_kernel<<<NBLOCKS, 128>>>(rbf, sph, m, w, (float*)d_out, nEdges);
}